// round 11
// baseline (speedup 1.0000x reference)
#include <cuda_runtime.h>
#include <math.h>

// Problem constants
#define S     64
#define SS    (S*S)          // 4096
#define SSS   (S*S*S)        // 262144
#define C_IN  16
#define C_HID 64
#define NELEM (C_IN*SSS)     // 4194304
#define NSTEPS 20
#define DT_F   0.05f

#define ICC   4              // input-channel chunk (smaller -> deeper pipeline)
#define XPAD  20             // padded x-row (80B, 16B-aligned)

// conv1: tile 16x4x4, 4 chunks
#define NCH1   (C_IN/ICC)            // 4
#define SIN1C  (ICC*6*6*XPAD)        // 2880 floats
#define SW1C   (ICC*27*C_HID)        // 6912 floats
#define CH1    (SIN1C + SW1C)        // 9792 floats per buffer
// conv2: tile 16x8x8, 16 chunks
#define NCH2   (C_HID/ICC)           // 16
#define SIN2C  (ICC*10*10*XPAD)      // 8000 floats
#define SW2C   (ICC*27*C_IN)         // 1728 floats
#define CH2    (SIN2C + SW2C)        // 9728 floats per buffer

// Scratch (device globals: allocation-free rule)
__device__ float g_y[NELEM];
__device__ float g_h[C_HID*SSS];
__device__ float g_w1r[C_IN*27*C_HID];   // [ic][tap][oc]
__device__ float g_w2r[C_HID*27*C_IN];   // [ic][tap][oc]

// ---- packed f32x2 helpers ----
__device__ __forceinline__ unsigned long long dupf(float v) {
    unsigned long long r;
    asm("mov.b64 %0, {%1, %1};" : "=l"(r) : "f"(v));
    return r;
}
__device__ __forceinline__ void ffma2(unsigned long long& acc,
                                      unsigned long long a,
                                      unsigned long long b) {
    asm("fma.rn.f32x2 %0, %1, %2, %0;" : "+l"(acc) : "l"(a), "l"(b));
}
__device__ __forceinline__ float2 unpack2(unsigned long long v) {
    float2 f;
    asm("mov.b64 {%0, %1}, %2;" : "=f"(f.x), "=f"(f.y) : "l"(v));
    return f;
}

// ---- cp.async helpers ----
__device__ __forceinline__ void cp4(unsigned int dst, const void* src) {
    asm volatile("cp.async.ca.shared.global [%0], [%1], 4;"
                 :: "r"(dst), "l"(src));
}
__device__ __forceinline__ void cp16(unsigned int dst, const void* src) {
    asm volatile("cp.async.cg.shared.global [%0], [%1], 16;"
                 :: "r"(dst), "l"(src));
}
__device__ __forceinline__ void cp_commit() {
    asm volatile("cp.async.commit_group;");
}
template<int N> __device__ __forceinline__ void cp_wait() {
    asm volatile("cp.async.wait_group %0;" :: "n"(N));
}
__device__ __forceinline__ void sts1(unsigned int dst, float v) {
    asm volatile("st.shared.f32 [%0], %1;" :: "r"(dst), "f"(v));
}

// ---------------------------------------------------------------------------
// Reorder weights: w[oc][ic][tap] -> wr[ic][tap][oc]
// ---------------------------------------------------------------------------
__global__ void reorder_w_kernel(const float* __restrict__ w1,
                                 const float* __restrict__ w2) {
    int i = blockIdx.x * blockDim.x + threadIdx.x;
    if (i >= C_IN*27*C_HID) return;
    {
        int oc = i & 63; int t = i >> 6; int tap = t % 27; int ic = t / 27;
        g_w1r[i] = w1[(oc*C_IN + ic)*27 + tap];
    }
    {
        int oc = i & 15; int t = i >> 4; int tap = t % 27; int ic = t / 27;
        g_w2r[i] = w2[(oc*C_HID + ic)*27 + tap];
    }
}

// ---------------------------------------------------------------------------
// Chunk loaders (cp.async; caller commits the group)
// ---------------------------------------------------------------------------
// conv1 input: [ICC][6][6][18] halo tile from yin, chunk base channel ic0.
__device__ __forceinline__ void load_in1(unsigned int sb,
                                         const float* __restrict__ src,
                                         int ic0, int x0, int y0, int z0,
                                         int tid) {
    for (int i = tid; i < ICC*6*6*18; i += 256) {
        int xi = i % 18; int r = i / 18;
        int yi = r % 6;  int zi = (r / 6) % 6;  int ici = r / 36;
        int gx = x0 + xi - 1, gy = y0 + yi - 1, gz = z0 + zi - 1;
        unsigned int dst = sb + (unsigned)((((ici*6 + zi)*6 + yi)*XPAD + xi)*4);
        if ((unsigned)gx < S && (unsigned)gy < S && (unsigned)gz < S)
            cp4(dst, &src[(ic0 + ici)*SSS + gz*SS + gy*S + gx]);
        else
            sts1(dst, 0.f);
    }
}
// conv2 input: [ICC][10][10][18]
__device__ __forceinline__ void load_in2(unsigned int sb,
                                         const float* __restrict__ src,
                                         int ic0, int x0, int y0, int z0,
                                         int tid) {
    for (int i = tid; i < ICC*10*10*18; i += 256) {
        int xi = i % 18; int r = i / 18;
        int yi = r % 10; int zi = (r / 10) % 10;  int ici = r / 100;
        int gx = x0 + xi - 1, gy = y0 + yi - 1, gz = z0 + zi - 1;
        unsigned int dst = sb + (unsigned)((((ici*10 + zi)*10 + yi)*XPAD + xi)*4);
        if ((unsigned)gx < S && (unsigned)gy < S && (unsigned)gz < S)
            cp4(dst, &src[(ic0 + ici)*SSS + gz*SS + gy*S + gx]);
        else
            sts1(dst, 0.f);
    }
}
// contiguous aligned weight slice, n16 = count of 16B units
__device__ __forceinline__ void load_w(unsigned int sb,
                                       const float* __restrict__ src,
                                       int n16, int tid) {
    for (int i = tid; i < n16; i += 256)
        cp16(sb + (unsigned)(i*16), src + i*4);
}

// ---------------------------------------------------------------------------
// Conv1 (16 -> 64) + tanh.  Tile 16x4x4.  256 threads.  Pipelined chunks.
//   og = tid>>5 (warp) -> 8 oc; weight LDS is pure broadcast
//   vg = tid&31 -> 8 x-voxels: xg in {0,1}, yy 0..3, zz 0..3
// ---------------------------------------------------------------------------
__global__ __launch_bounds__(256, 2)
void conv1_tanh_kernel(const float* __restrict__ yin,
                       float* __restrict__ hout,
                       const float* __restrict__ b1) {
    extern __shared__ float sm[];

    const int tid = threadIdx.x;
    const int og  = tid >> 5;
    const int vg  = tid & 31;
    const int xg  = vg & 1;
    const int yy  = (vg >> 1) & 3;
    const int zz  = vg >> 3;
    const int x0  = blockIdx.x * 16;
    const int y0  = blockIdx.y * 4;
    const int z0  = blockIdx.z * 4;

    const unsigned int sb0 =
        (unsigned int)__cvta_generic_to_shared(sm);

    unsigned long long acc2[32];
    #pragma unroll
    for (int i = 0; i < 32; i++) acc2[i] = 0ull;

    // preload chunks 0,1
    #pragma unroll
    for (int p = 0; p < 2; p++) {
        unsigned int sb = sb0 + (unsigned)(p*CH1*4);
        load_in1(sb, yin, p*ICC, x0, y0, z0, tid);
        load_w(sb + SIN1C*4, g_w1r + p*ICC*27*C_HID, SW1C/4, tid);
        cp_commit();
    }

    for (int c = 0; c < NCH1; c++) {
        if (c < NCH1 - 1) cp_wait<1>(); else cp_wait<0>();
        __syncthreads();

        const float* s_in = sm + (c & 1)*CH1;
        const float* s_w  = s_in + SIN1C;

        #pragma unroll 1
        for (int ici = 0; ici < ICC; ici++) {
            #pragma unroll 1
            for (int dz = 0; dz < 3; dz++) {
                #pragma unroll
                for (int dy = 0; dy < 3; dy++) {
                    const float* base =
                        &s_in[((ici*6 + zz + dz)*6 + yy + dy)*XPAD + xg*8];
                    float4 ra = *(const float4*)(base);
                    float4 rb = *(const float4*)(base + 4);
                    float2 rc = *(const float2*)(base + 8);
                    float rr[10] = {ra.x,ra.y,ra.z,ra.w,
                                    rb.x,rb.y,rb.z,rb.w, rc.x,rc.y};
                    unsigned long long din[10];
                    #pragma unroll
                    for (int k = 0; k < 10; k++) din[k] = dupf(rr[k]);
                    #pragma unroll
                    for (int dx = 0; dx < 3; dx++) {
                        const ulonglong2* wp = (const ulonglong2*)
                            &s_w[((ici*27 + (dz*3 + dy)*3 + dx) << 6) + og*8];
                        ulonglong2 wa = wp[0];
                        ulonglong2 wb = wp[1];
                        #pragma unroll
                        for (int v = 0; v < 8; v++) {
                            unsigned long long in2 = din[dx + v];
                            ffma2(acc2[v*4 + 0], in2, wa.x);
                            ffma2(acc2[v*4 + 1], in2, wa.y);
                            ffma2(acc2[v*4 + 2], in2, wb.x);
                            ffma2(acc2[v*4 + 3], in2, wb.y);
                        }
                    }
                }
            }
        }
        __syncthreads();
        if (c + 2 < NCH1) {
            unsigned int sb = sb0 + (unsigned)((c & 1)*CH1*4);
            load_in1(sb, yin, (c + 2)*ICC, x0, y0, z0, tid);
            load_w(sb + SIN1C*4, g_w1r + (c + 2)*ICC*27*C_HID, SW1C/4, tid);
            cp_commit();
        }
    }

    // bias + tanh + vectorized store (8 oc x 8 voxels)
    const int ox = x0 + xg*8, oy = y0 + yy, oz = z0 + zz;
    #pragma unroll
    for (int op = 0; op < 4; op++) {
        int oce = og*8 + 2*op;
        float bl = b1[oce], bh = b1[oce + 1];
        float2 p[8];
        #pragma unroll
        for (int v = 0; v < 8; v++) p[v] = unpack2(acc2[v*4 + op]);
        float4 e0, e1, o0, o1;
        e0.x = tanhf(p[0].x + bl); e0.y = tanhf(p[1].x + bl);
        e0.z = tanhf(p[2].x + bl); e0.w = tanhf(p[3].x + bl);
        e1.x = tanhf(p[4].x + bl); e1.y = tanhf(p[5].x + bl);
        e1.z = tanhf(p[6].x + bl); e1.w = tanhf(p[7].x + bl);
        o0.x = tanhf(p[0].y + bh); o0.y = tanhf(p[1].y + bh);
        o0.z = tanhf(p[2].y + bh); o0.w = tanhf(p[3].y + bh);
        o1.x = tanhf(p[4].y + bh); o1.y = tanhf(p[5].y + bh);
        o1.z = tanhf(p[6].y + bh); o1.w = tanhf(p[7].y + bh);
        float* pe = &hout[oce*SSS + oz*SS + oy*S + ox];
        *(float4*)pe             = e0;
        *(float4*)(pe + 4)       = e1;
        *(float4*)(pe + SSS)     = o0;
        *(float4*)(pe + SSS + 4) = o1;
    }
}

// ---------------------------------------------------------------------------
// Conv2 (64 -> 16) + Euler update.  Tile 16x8x8.  256 threads.  Pipelined.
//   og = tid>>7 (0/1) -> 8 oc; constant per warp -> weight broadcast
//   vg = tid&127 -> xg in {0,1}, yy 0..7, zz 0..7
// ---------------------------------------------------------------------------
__global__ __launch_bounds__(256, 2)
void conv2_update_kernel(const float* __restrict__ hin,
                         float* __restrict__ yio,
                         const float* __restrict__ b2,
                         const float* __restrict__ nz) {
    extern __shared__ float sm[];

    const int tid = threadIdx.x;
    const int og  = tid >> 7;
    const int vg  = tid & 127;
    const int xg  = vg & 1;
    const int yy  = (vg >> 1) & 7;
    const int zz  = vg >> 4;
    const int x0  = blockIdx.x * 16;
    const int y0  = blockIdx.y * 8;
    const int z0  = blockIdx.z * 8;

    const unsigned int sb0 =
        (unsigned int)__cvta_generic_to_shared(sm);

    unsigned long long acc2[32];
    #pragma unroll
    for (int i = 0; i < 32; i++) acc2[i] = 0ull;

    #pragma unroll
    for (int p = 0; p < 2; p++) {
        unsigned int sb = sb0 + (unsigned)(p*CH2*4);
        load_in2(sb, hin, p*ICC, x0, y0, z0, tid);
        load_w(sb + SIN2C*4, g_w2r + p*ICC*27*C_IN, SW2C/4, tid);
        cp_commit();
    }

    for (int c = 0; c < NCH2; c++) {
        if (c < NCH2 - 1) cp_wait<1>(); else cp_wait<0>();
        __syncthreads();

        const float* s_in = sm + (c & 1)*CH2;
        const float* s_w  = s_in + SIN2C;

        #pragma unroll 1
        for (int ici = 0; ici < ICC; ici++) {
            #pragma unroll 1
            for (int dz = 0; dz < 3; dz++) {
                #pragma unroll
                for (int dy = 0; dy < 3; dy++) {
                    const float* base =
                        &s_in[((ici*10 + zz + dz)*10 + yy + dy)*XPAD + xg*8];
                    float4 ra = *(const float4*)(base);
                    float4 rb = *(const float4*)(base + 4);
                    float2 rc = *(const float2*)(base + 8);
                    float rr[10] = {ra.x,ra.y,ra.z,ra.w,
                                    rb.x,rb.y,rb.z,rb.w, rc.x,rc.y};
                    unsigned long long din[10];
                    #pragma unroll
                    for (int k = 0; k < 10; k++) din[k] = dupf(rr[k]);
                    #pragma unroll
                    for (int dx = 0; dx < 3; dx++) {
                        const ulonglong2* wp = (const ulonglong2*)
                            &s_w[((ici*27 + (dz*3 + dy)*3 + dx) << 4) + og*8];
                        ulonglong2 wa = wp[0];
                        ulonglong2 wb = wp[1];
                        #pragma unroll
                        for (int v = 0; v < 8; v++) {
                            unsigned long long in2 = din[dx + v];
                            ffma2(acc2[v*4 + 0], in2, wa.x);
                            ffma2(acc2[v*4 + 1], in2, wa.y);
                            ffma2(acc2[v*4 + 2], in2, wb.x);
                            ffma2(acc2[v*4 + 3], in2, wb.y);
                        }
                    }
                }
            }
        }
        __syncthreads();
        if (c + 2 < NCH2) {
            unsigned int sb = sb0 + (unsigned)((c & 1)*CH2*4);
            load_in2(sb, hin, (c + 2)*ICC, x0, y0, z0, tid);
            load_w(sb + SIN2C*4, g_w2r + (c + 2)*ICC*27*C_IN, SW2C/4, tid);
            cp_commit();
        }
    }

    // Euler-Maruyama update (in-place on y; pointwise -> safe)
    const float sn = 0.1f * 0.22360679774997896f;   // sigma * sqrt(dt)
    const int ox = x0 + xg*8, oy = y0 + yy, oz = z0 + zz;
    #pragma unroll
    for (int op = 0; op < 4; op++) {
        int oce = og*8 + 2*op;
        float bl = b2[oce], bh = b2[oce + 1];
        float2 p[8];
        #pragma unroll
        for (int v = 0; v < 8; v++) p[v] = unpack2(acc2[v*4 + op]);

        int ide = oce*SSS + oz*SS + oy*S + ox;
        int ido = ide + SSS;
        float4 ye0 = *(const float4*)&yio[ide];
        float4 ye1 = *(const float4*)&yio[ide + 4];
        float4 yo0 = *(const float4*)&yio[ido];
        float4 yo1 = *(const float4*)&yio[ido + 4];
        float4 ze0 = *(const float4*)&nz[ide];
        float4 ze1 = *(const float4*)&nz[ide + 4];
        float4 zo0 = *(const float4*)&nz[ido];
        float4 zo1 = *(const float4*)&nz[ido + 4];
        float4 r0, r1, r2, r3;
        r0.x = ye0.x + (p[0].x + bl)*DT_F + sn*ze0.x;
        r0.y = ye0.y + (p[1].x + bl)*DT_F + sn*ze0.y;
        r0.z = ye0.z + (p[2].x + bl)*DT_F + sn*ze0.z;
        r0.w = ye0.w + (p[3].x + bl)*DT_F + sn*ze0.w;
        r1.x = ye1.x + (p[4].x + bl)*DT_F + sn*ze1.x;
        r1.y = ye1.y + (p[5].x + bl)*DT_F + sn*ze1.y;
        r1.z = ye1.z + (p[6].x + bl)*DT_F + sn*ze1.z;
        r1.w = ye1.w + (p[7].x + bl)*DT_F + sn*ze1.w;
        r2.x = yo0.x + (p[0].y + bh)*DT_F + sn*zo0.x;
        r2.y = yo0.y + (p[1].y + bh)*DT_F + sn*zo0.y;
        r2.z = yo0.z + (p[2].y + bh)*DT_F + sn*zo0.z;
        r2.w = yo0.w + (p[3].y + bh)*DT_F + sn*zo0.w;
        r3.x = yo1.x + (p[4].y + bh)*DT_F + sn*zo1.x;
        r3.y = yo1.y + (p[5].y + bh)*DT_F + sn*zo1.y;
        r3.z = yo1.z + (p[6].y + bh)*DT_F + sn*zo1.z;
        r3.w = yo1.w + (p[7].y + bh)*DT_F + sn*zo1.w;
        *(float4*)&yio[ide]     = r0;
        *(float4*)&yio[ide + 4] = r1;
        *(float4*)&yio[ido]     = r2;
        *(float4*)&yio[ido + 4] = r3;
    }
}

// ---------------------------------------------------------------------------
// Launch: inputs = [x, integration_time, w1, b1, w2, b2, noise]
// ---------------------------------------------------------------------------
extern "C" void kernel_launch(void* const* d_in, const int* in_sizes, int n_in,
                              void* d_out, int out_size) {
    const float* x  = (const float*)d_in[0];
    const float* w1 = (const float*)d_in[2];
    const float* b1 = (const float*)d_in[3];
    const float* w2 = (const float*)d_in[4];
    const float* b2 = (const float*)d_in[5];
    const float* nz = (const float*)d_in[6];

    float *yp, *hp;
    cudaGetSymbolAddress((void**)&yp, g_y);
    cudaGetSymbolAddress((void**)&hp, g_h);

    const int smem1 = 2 * CH1 * (int)sizeof(float);  // 78336 B
    const int smem2 = 2 * CH2 * (int)sizeof(float);  // 77824 B
    cudaFuncSetAttribute(conv1_tanh_kernel,
                         cudaFuncAttributeMaxDynamicSharedMemorySize, smem1);
    cudaFuncSetAttribute(conv2_update_kernel,
                         cudaFuncAttributeMaxDynamicSharedMemorySize, smem2);

    cudaMemcpyAsync(yp, x, (size_t)NELEM * sizeof(float),
                    cudaMemcpyDeviceToDevice, 0);

    reorder_w_kernel<<<(C_IN*27*C_HID + 255)/256, 256>>>(w1, w2);

    dim3 grid1(S/16, S/4, S/4);   // (4,16,16) = 1024 blocks
    dim3 grid2(S/16, S/8, S/8);   // (4,8,8)   = 256 blocks
    for (int s = 0; s < NSTEPS; s++) {
        conv1_tanh_kernel<<<grid1, 256, smem1>>>(yp, hp, b1);
        conv2_update_kernel<<<grid2, 256, smem2>>>(hp, yp, b2,
                                                   nz + (size_t)s * NELEM);
    }

    cudaMemcpyAsync(d_out, yp, (size_t)NELEM * sizeof(float),
                    cudaMemcpyDeviceToDevice, 0);
}

// round 12
// speedup vs baseline: 1.7973x; 1.7973x over previous
#include <cuda_runtime.h>
#include <math.h>
#include <stdint.h>

// ---------------- problem constants ----------------
#define S     64
#define SS    (S*S)
#define SSS   (S*S*S)
#define C_IN  16
#define C_HID 64
#define NELEM (C_IN*SSS)       // 4194304
#define NSTEPS 20
#define DT_F   0.05f
#define SN_F   (0.1f * 0.22360679774997896f)

#define PD    66               // padded side (zero shell)
#define PCH   (PD*PD*PD)       // 287496 voxels padded
#define HCH   (PCH*8)          // floats per 8-channel h chunk

// conv tiles: CTA covers x:64, y:2, z:1  (M = 128 voxels), 8 warps
// warp: 16 consecutive x-voxels, all oc
#define T1ROW 5280             // 66*20*4 bytes per (z,y) row, conv1 tile
#define T1SZ  63360            // 12 rows
#define T2ROW 3168             // 66*12*4
#define T2SZ  38016            // 12 rows (one 8-ic chunk)

// ---------------- device scratch (allocation-free; zero-init shells) -------
__device__ float g_ypad[PCH*16];        // y, padded channels-last [z][y][x][16]
__device__ float g_h[HCH*8];            // h, 8 chunks of [z][y][x][8] (tf32-rounded)
__device__ float g_f[NELEM];            // conv2 raw output, compact CL [z][y][x][16]
__device__ float g_wf1[27*2*8*32*2];    // conv1 B-frags [tap][ks][nt][lane][2]
__device__ float g_wf2[8*27*2*32*2];    // conv2 B-frags [ch][tap][nt][lane][2]

// ---------------- PTX helpers ----------------
__device__ __forceinline__ uint32_t cvt_tf32(float f) {
    uint32_t r;
    asm("cvt.rna.tf32.f32 %0, %1;" : "=r"(r) : "f"(f));
    return r;
}
__device__ __forceinline__ float lds_f(uint32_t a) {
    float v;
    asm volatile("ld.shared.f32 %0, [%1];" : "=f"(v) : "r"(a));
    return v;
}
__device__ __forceinline__ void mma_tf32(float* d, uint32_t a0, uint32_t a1,
                                         uint32_t a2, uint32_t a3,
                                         uint32_t b0, uint32_t b1) {
    asm volatile(
        "mma.sync.aligned.m16n8k8.row.col.f32.tf32.tf32.f32 "
        "{%0,%1,%2,%3}, {%4,%5,%6,%7}, {%8,%9}, {%0,%1,%2,%3};"
        : "+f"(d[0]), "+f"(d[1]), "+f"(d[2]), "+f"(d[3])
        : "r"(a0), "r"(a1), "r"(a2), "r"(a3), "r"(b0), "r"(b1));
}
__device__ __forceinline__ void cp16(uint32_t dst, const void* src) {
    asm volatile("cp.async.cg.shared.global [%0], [%1], 16;"
                 :: "r"(dst), "l"(src));
}
__device__ __forceinline__ void cp_commit() {
    asm volatile("cp.async.commit_group;");
}
template<int N> __device__ __forceinline__ void cp_wait() {
    asm volatile("cp.async.wait_group %0;" :: "n"(N));
}

// ---------------------------------------------------------------------------
// Weight reorder into mma B-fragment layout (tf32-rounded).
//   wf1[tap][ks][nt][lane][j]: B[k = lane%4 + j*4 (+ks*8 ic)][n = nt*8 + lane/4]
// ---------------------------------------------------------------------------
__global__ void reorder_k(const float* __restrict__ w1,
                          const float* __restrict__ w2) {
    int i = blockIdx.x * blockDim.x + threadIdx.x;
    if (i >= 27648) return;
    {   // conv1: w1[oc64][ic16][27]
        int j = i & 1, lane = (i >> 1) & 31, nt = (i >> 6) & 7,
            ks = (i >> 9) & 1, tap = i >> 10;
        int oc = nt * 8 + (lane >> 2);
        int ic = ks * 8 + (lane & 3) + j * 4;
        uint32_t v = cvt_tf32(w1[(oc * 16 + ic) * 27 + tap]);
        g_wf1[i] = __uint_as_float(v);
    }
    {   // conv2: w2[oc16][ic64][27]
        int j = i & 1, lane = (i >> 1) & 31, nt = (i >> 6) & 1;
        int t2 = i >> 7, tap = t2 % 27, ch = t2 / 27;
        int oc = nt * 8 + (lane >> 2);
        int ic = ch * 8 + (lane & 3) + j * 4;
        uint32_t v = cvt_tf32(w2[(oc * 64 + ic) * 27 + tap]);
        g_wf2[i] = __uint_as_float(v);
    }
}

// ---------------------------------------------------------------------------
// Pack: x standard [c][z][y][x] -> g_ypad padded CL [z+1][y+1][x+1][c]
// ---------------------------------------------------------------------------
__global__ void pack_k(const float* __restrict__ xin) {
    int e = blockIdx.x * blockDim.x + threadIdx.x;
    if (e >= NELEM) return;
    int c = e & 15, v = e >> 4;
    int x = v & 63, y = (v >> 6) & 63, z = v >> 12;
    g_ypad[((((z + 1) * PD) + y + 1) * PD + x + 1) * 16 + c] = xin[c * SSS + v];
}
__global__ void unpack_k(float* __restrict__ out) {
    int e = blockIdx.x * blockDim.x + threadIdx.x;
    if (e >= NELEM) return;
    int c = e & 15, v = e >> 4;
    int x = v & 63, y = (v >> 6) & 63, z = v >> 12;
    out[c * SSS + v] = g_ypad[((((z + 1) * PD) + y + 1) * PD + x + 1) * 16 + c];
}

// ---------------------------------------------------------------------------
// Conv1 (16 -> 64) + bias + tanh -> g_h (tf32-rounded, chunked CL).
// grid (32 ytile, 64 z), 256 threads, smem T1SZ.
// ---------------------------------------------------------------------------
__global__ __launch_bounds__(256, 2)
void conv1_k(const float* __restrict__ b1) {
    extern __shared__ float sm[];
    const int tid = threadIdx.x, lane = tid & 31, w = tid >> 5;
    const int x0w = (w & 3) * 16, yw = w >> 2;
    const int y0 = blockIdx.x * 2, z0 = blockIdx.y;

    const uint32_t tb = (uint32_t)__cvta_generic_to_shared(sm);

    // load tile: 12 rows x 66 vox x 16 ch
    for (int i = tid; i < 12 * 66; i += 256) {
        int row = i / 66, xp = i % 66;
        int zi = row >> 2, yi = row & 3;
        const float* src = g_ypad +
            ((((z0 + zi) * PD) + y0 + yi) * PD + xp) * 16;
        uint32_t dst = tb + (uint32_t)(row * T1ROW + xp * 80);
        cp16(dst,      src);
        cp16(dst + 16, src + 4);
        cp16(dst + 32, src + 8);
        cp16(dst + 48, src + 12);
    }
    cp_commit(); cp_wait<0>();
    __syncthreads();

    // bias-init D frags: d[nt][0..3]; cols c0 = nt*8 + (lane%4)*2
    float d[8][4];
    const int c0 = (lane & 3) * 2;
    #pragma unroll
    for (int nt = 0; nt < 8; nt++) {
        float bl = __ldg(b1 + nt * 8 + c0), bh = __ldg(b1 + nt * 8 + c0 + 1);
        d[nt][0] = bl; d[nt][1] = bh; d[nt][2] = bl; d[nt][3] = bh;
    }

    const uint32_t loff = (uint32_t)((lane >> 2) * 80 + (lane & 3) * 4);

    #pragma unroll 1
    for (int dz = 0; dz < 3; dz++) {
        #pragma unroll 1
        for (int dy = 0; dy < 3; dy++) {
            const uint32_t rbase = tb + (uint32_t)((dz * 4 + yw + dy) * T1ROW);
            const int tap = (dz * 3 + dy) * 3;
            #pragma unroll
            for (int dx = 0; dx < 3; dx++) {
                const uint32_t ab = rbase + (uint32_t)((x0w + dx) * 80) + loff;
                const float* wb = g_wf1 + (tap + dx) * 1024 + lane * 2;
                #pragma unroll
                for (int ks = 0; ks < 2; ks++) {
                    uint32_t a0 = cvt_tf32(lds_f(ab + ks * 32));
                    uint32_t a2 = cvt_tf32(lds_f(ab + ks * 32 + 16));
                    uint32_t a1 = cvt_tf32(lds_f(ab + ks * 32 + 640));
                    uint32_t a3 = cvt_tf32(lds_f(ab + ks * 32 + 656));
                    const float* wk = wb + ks * 512;
                    #pragma unroll
                    for (int nt = 0; nt < 8; nt++) {
                        uint2 b = __ldg((const uint2*)(wk + nt * 64));
                        mma_tf32(d[nt], a0, a1, a2, a3, b.x, b.y);
                    }
                }
            }
        }
    }

    // epilogue: tanh + tf32-round, store to h chunks
    const int zp = z0 + 1, yp = y0 + yw + 1;
    const int hrow = ((zp * PD + yp) * PD + 1 + x0w) * 8 + (lane >> 2) * 8 + c0;
    #pragma unroll
    for (int nt = 0; nt < 8; nt++) {
        int a0i = nt * HCH + hrow;
        float2 lo, hi;
        lo.x = __uint_as_float(cvt_tf32(tanhf(d[nt][0])));
        lo.y = __uint_as_float(cvt_tf32(tanhf(d[nt][1])));
        hi.x = __uint_as_float(cvt_tf32(tanhf(d[nt][2])));
        hi.y = __uint_as_float(cvt_tf32(tanhf(d[nt][3])));
        *(float2*)&g_h[a0i]      = lo;
        *(float2*)&g_h[a0i + 64] = hi;   // +8 voxels * 8 ch
    }
}

// ---------------------------------------------------------------------------
// Conv2 (64 -> 16), raw output -> g_f (compact CL). 8 ic-chunks, double-buffered.
// ---------------------------------------------------------------------------
__device__ __forceinline__ void load_chunk2(uint32_t buf, int ch,
                                            int y0, int z0, int tid) {
    const float* base = g_h + ch * HCH;
    for (int i = tid; i < 12 * 66; i += 256) {
        int row = i / 66, xp = i % 66;
        int zi = row >> 2, yi = row & 3;
        const float* src = base + ((((z0 + zi) * PD) + y0 + yi) * PD + xp) * 8;
        uint32_t dst = buf + (uint32_t)(row * T2ROW + xp * 48);
        cp16(dst,      src);
        cp16(dst + 16, src + 4);
    }
}

__global__ __launch_bounds__(256, 2)
void conv2_k() {
    extern __shared__ float sm[];
    const int tid = threadIdx.x, lane = tid & 31, w = tid >> 5;
    const int x0w = (w & 3) * 16, yw = w >> 2;
    const int y0 = blockIdx.x * 2, z0 = blockIdx.y;

    const uint32_t tb = (uint32_t)__cvta_generic_to_shared(sm);

    float d[2][4];
    #pragma unroll
    for (int nt = 0; nt < 2; nt++)
        d[nt][0] = d[nt][1] = d[nt][2] = d[nt][3] = 0.f;

    const uint32_t loff = (uint32_t)((lane >> 2) * 48 + (lane & 3) * 4);

    load_chunk2(tb, 0, y0, z0, tid);
    cp_commit();

    #pragma unroll 1
    for (int ch = 0; ch < 8; ch++) {
        __syncthreads();                      // prev compute done on target buf
        if (ch + 1 < 8) {
            load_chunk2(tb + (uint32_t)(((ch + 1) & 1) * T2SZ),
                        ch + 1, y0, z0, tid);
            cp_commit();
            cp_wait<1>();
        } else {
            cp_wait<0>();
        }
        __syncthreads();                      // chunk ch resident

        const uint32_t cb = tb + (uint32_t)((ch & 1) * T2SZ);
        const float* wch = g_wf2 + ch * 3456 + lane * 2;   // 27*2*64

        #pragma unroll 1
        for (int dz = 0; dz < 3; dz++) {
            #pragma unroll
            for (int dy = 0; dy < 3; dy++) {
                const uint32_t rbase = cb + (uint32_t)((dz * 4 + yw + dy) * T2ROW);
                const int tap = (dz * 3 + dy) * 3;
                #pragma unroll
                for (int dx = 0; dx < 3; dx++) {
                    const uint32_t ab = rbase + (uint32_t)((x0w + dx) * 48) + loff;
                    uint32_t a0 = cvt_tf32(lds_f(ab));
                    uint32_t a2 = cvt_tf32(lds_f(ab + 16));
                    uint32_t a1 = cvt_tf32(lds_f(ab + 384));
                    uint32_t a3 = cvt_tf32(lds_f(ab + 400));
                    const float* wt = wch + (tap + dx) * 128;
                    uint2 b0 = __ldg((const uint2*)(wt));
                    uint2 b1 = __ldg((const uint2*)(wt + 64));
                    mma_tf32(d[0], a0, a1, a2, a3, b0.x, b0.y);
                    mma_tf32(d[1], a0, a1, a2, a3, b1.x, b1.y);
                }
            }
        }
    }

    // epilogue: raw f, compact CL [z][y][x][16]
    const int c0 = (lane & 3) * 2;
    const int base = (((z0 * 64) + y0 + yw) * 64 + x0w) * 16 + (lane >> 2) * 16;
    #pragma unroll
    for (int nt = 0; nt < 2; nt++) {
        int a0i = base + nt * 8 + c0;
        *(float2*)&g_f[a0i]       = make_float2(d[nt][0], d[nt][1]);
        *(float2*)&g_f[a0i + 128] = make_float2(d[nt][2], d[nt][3]);  // +8 vox
    }
}

// ---------------------------------------------------------------------------
// Euler update: y += (f + b2)*dt + sn*z.   grid (64 z, 32 ypair), 256 thr.
// ---------------------------------------------------------------------------
__global__ void update_k(const float* __restrict__ b2,
                         const float* __restrict__ nz) {
    __shared__ float s_nz[2 * 16 * 65];
    const int tid = threadIdx.x;
    const int z = blockIdx.x, y0 = blockIdx.y * 2;

    for (int j = tid; j < 2048; j += 256) {
        int yloc = j >> 10, rem = j & 1023, c = rem >> 6, x = rem & 63;
        s_nz[yloc * 1040 + c * 65 + x] =
            nz[c * SSS + (z * 64 + y0 + yloc) * 64 + x];
    }
    __syncthreads();

    for (int e = tid; e < 2048; e += 256) {
        int yloc = e >> 10, rem = e & 1023, v = rem >> 4, c = rem & 15;
        int gy = y0 + yloc;
        int fi = (((z * 64) + gy) * 64 + v) * 16 + c;
        int yi = ((((z + 1) * PD) + gy + 1) * PD + v + 1) * 16 + c;
        g_ypad[yi] += (g_f[fi] + b2[c]) * DT_F
                      + SN_F * s_nz[yloc * 1040 + c * 65 + v];
    }
}

// ---------------------------------------------------------------------------
// Launch: inputs = [x, integration_time, w1, b1, w2, b2, noise]
// ---------------------------------------------------------------------------
extern "C" void kernel_launch(void* const* d_in, const int* in_sizes, int n_in,
                              void* d_out, int out_size) {
    const float* x  = (const float*)d_in[0];
    const float* w1 = (const float*)d_in[2];
    const float* b1 = (const float*)d_in[3];
    const float* w2 = (const float*)d_in[4];
    const float* b2 = (const float*)d_in[5];
    const float* nz = (const float*)d_in[6];

    cudaFuncSetAttribute(conv1_k,
        cudaFuncAttributeMaxDynamicSharedMemorySize, T1SZ);
    cudaFuncSetAttribute(conv2_k,
        cudaFuncAttributeMaxDynamicSharedMemorySize, 2 * T2SZ);

    reorder_k<<<(27648 + 255) / 256, 256>>>(w1, w2);
    pack_k<<<NELEM / 256, 256>>>(x);

    dim3 cgrid(32, 64);
    dim3 ugrid(64, 32);
    for (int s = 0; s < NSTEPS; s++) {
        conv1_k<<<cgrid, 256, T1SZ>>>(b1);
        conv2_k<<<cgrid, 256, 2 * T2SZ>>>();
        update_k<<<ugrid, 256>>>(b2, nz + (size_t)s * NELEM);
    }

    unpack_k<<<NELEM / 256, 256>>>((float*)d_out);
}

// round 13
// speedup vs baseline: 1.9323x; 1.0751x over previous
#include <cuda_runtime.h>
#include <math.h>
#include <stdint.h>

// ---------------- problem constants ----------------
#define S     64
#define SS    (S*S)
#define SSS   (S*S*S)
#define C_IN  16
#define C_HID 64
#define NELEM (C_IN*SSS)       // 4194304
#define NSTEPS 20
#define DT_F   0.05f
#define SN_F   (0.1f * 0.22360679774997896f)

#define PD    66               // padded side (zero shell)
#define PCH   (PD*PD*PD)       // 287496 voxels padded
#define HCH   (PCH*8)          // floats per 8-channel h chunk

// conv tiles: CTA covers x:64, y:2, z:1  (M = 128 voxels), 8 warps
#define T1ROW 5280             // 66*20*4 bytes per (z,y) row, conv1 tile
#define T1SZ  63360            // 12 rows
#define T2ROW 3168             // 66*12*4
#define T2SZ  38016            // 12 rows (one 8-ic chunk)

// ---------------- device scratch (allocation-free; zero-init shells) -------
__device__ float g_ypad[PCH*16];        // y fp32 state, padded CL [z][y][x][16]
__device__ float g_ytf32[PCH*16];       // tf32-rounded shadow of y (conv1 input)
__device__ float g_h[HCH*8];            // h, 8 chunks of [z][y][x][8] (tf32 bits)
__device__ float g_wf1[27*2*8*32*2];    // conv1 B-frags [tap][ks][nt][lane][2]
__device__ float g_wf2[8*27*2*32*2];    // conv2 B-frags [ch][tap][nt][lane][2]

// ---------------- PTX helpers ----------------
__device__ __forceinline__ uint32_t cvt_tf32(float f) {
    uint32_t r;
    asm("cvt.rna.tf32.f32 %0, %1;" : "=r"(r) : "f"(f));
    return r;
}
__device__ __forceinline__ uint32_t lds_u(uint32_t a) {
    uint32_t v;
    asm volatile("ld.shared.b32 %0, [%1];" : "=r"(v) : "r"(a));
    return v;
}
__device__ __forceinline__ void mma_tf32(float* d, uint32_t a0, uint32_t a1,
                                         uint32_t a2, uint32_t a3,
                                         uint32_t b0, uint32_t b1) {
    asm volatile(
        "mma.sync.aligned.m16n8k8.row.col.f32.tf32.tf32.f32 "
        "{%0,%1,%2,%3}, {%4,%5,%6,%7}, {%8,%9}, {%0,%1,%2,%3};"
        : "+f"(d[0]), "+f"(d[1]), "+f"(d[2]), "+f"(d[3])
        : "r"(a0), "r"(a1), "r"(a2), "r"(a3), "r"(b0), "r"(b1));
}
__device__ __forceinline__ void cp16(uint32_t dst, const void* src) {
    asm volatile("cp.async.cg.shared.global [%0], [%1], 16;"
                 :: "r"(dst), "l"(src));
}
__device__ __forceinline__ void cp_commit() {
    asm volatile("cp.async.commit_group;");
}
template<int N> __device__ __forceinline__ void cp_wait() {
    asm volatile("cp.async.wait_group %0;" :: "n"(N));
}

// ---------------------------------------------------------------------------
// Weight reorder into mma B-fragment layout (tf32-rounded).
// ---------------------------------------------------------------------------
__global__ void reorder_k(const float* __restrict__ w1,
                          const float* __restrict__ w2) {
    int i = blockIdx.x * blockDim.x + threadIdx.x;
    if (i >= 27648) return;
    {   // conv1: w1[oc64][ic16][27]
        int j = i & 1, lane = (i >> 1) & 31, nt = (i >> 6) & 7,
            ks = (i >> 9) & 1, tap = i >> 10;
        int oc = nt * 8 + (lane >> 2);
        int ic = ks * 8 + (lane & 3) + j * 4;
        g_wf1[i] = __uint_as_float(cvt_tf32(w1[(oc * 16 + ic) * 27 + tap]));
    }
    {   // conv2: w2[oc16][ic64][27]
        int j = i & 1, lane = (i >> 1) & 31, nt = (i >> 6) & 1;
        int t2 = i >> 7, tap = t2 % 27, ch = t2 / 27;
        int oc = nt * 8 + (lane >> 2);
        int ic = ch * 8 + (lane & 3) + j * 4;
        g_wf2[i] = __uint_as_float(cvt_tf32(w2[(oc * 64 + ic) * 27 + tap]));
    }
}

// ---------------------------------------------------------------------------
// Pack: x standard [c][z][y][x] -> padded CL (fp32 + tf32 shadow)
// ---------------------------------------------------------------------------
__global__ void pack_k(const float* __restrict__ xin) {
    int e = blockIdx.x * blockDim.x + threadIdx.x;
    if (e >= NELEM) return;
    int c = e & 15, v = e >> 4;
    int x = v & 63, y = (v >> 6) & 63, z = v >> 12;
    float val = xin[c * SSS + v];
    int pi = ((((z + 1) * PD) + y + 1) * PD + x + 1) * 16 + c;
    g_ypad[pi]  = val;
    g_ytf32[pi] = __uint_as_float(cvt_tf32(val));
}
__global__ void unpack_k(float* __restrict__ out) {
    int e = blockIdx.x * blockDim.x + threadIdx.x;
    if (e >= NELEM) return;
    int c = e & 15, v = e >> 4;
    int x = v & 63, y = (v >> 6) & 63, z = v >> 12;
    out[c * SSS + v] = g_ypad[((((z + 1) * PD) + y + 1) * PD + x + 1) * 16 + c];
}

// ---------------------------------------------------------------------------
// Conv1 (16 -> 64) + bias + tanh -> g_h (tf32 bits, chunked CL).
// Reads g_ytf32 (pre-rounded) -> no cvt in mainloop.
// ---------------------------------------------------------------------------
__global__ __launch_bounds__(256, 2)
void conv1_k(const float* __restrict__ b1) {
    extern __shared__ float sm[];
    const int tid = threadIdx.x, lane = tid & 31, w = tid >> 5;
    const int x0w = (w & 3) * 16, yw = w >> 2;
    const int y0 = blockIdx.x * 2, z0 = blockIdx.y;

    const uint32_t tb = (uint32_t)__cvta_generic_to_shared(sm);

    // load tile: 12 rows x 66 vox x 16 ch (from tf32 shadow)
    for (int i = tid; i < 12 * 66; i += 256) {
        int row = i / 66, xp = i % 66;
        int zi = row >> 2, yi = row & 3;
        const float* src = g_ytf32 +
            ((((z0 + zi) * PD) + y0 + yi) * PD + xp) * 16;
        uint32_t dst = tb + (uint32_t)(row * T1ROW + xp * 80);
        cp16(dst,      src);
        cp16(dst + 16, src + 4);
        cp16(dst + 32, src + 8);
        cp16(dst + 48, src + 12);
    }
    cp_commit(); cp_wait<0>();
    __syncthreads();

    float d[8][4];
    const int c0 = (lane & 3) * 2;
    #pragma unroll
    for (int nt = 0; nt < 8; nt++) {
        float bl = __ldg(b1 + nt * 8 + c0), bh = __ldg(b1 + nt * 8 + c0 + 1);
        d[nt][0] = bl; d[nt][1] = bh; d[nt][2] = bl; d[nt][3] = bh;
    }

    const uint32_t loff = (uint32_t)((lane >> 2) * 80 + (lane & 3) * 4);

    #pragma unroll 1
    for (int dz = 0; dz < 3; dz++) {
        #pragma unroll 1
        for (int dy = 0; dy < 3; dy++) {
            const uint32_t rbase = tb + (uint32_t)((dz * 4 + yw + dy) * T1ROW);
            const int tap = (dz * 3 + dy) * 3;
            #pragma unroll
            for (int dx = 0; dx < 3; dx++) {
                const uint32_t ab = rbase + (uint32_t)((x0w + dx) * 80) + loff;
                const float* wb = g_wf1 + (tap + dx) * 1024 + lane * 2;
                #pragma unroll
                for (int ks = 0; ks < 2; ks++) {
                    uint32_t a0 = lds_u(ab + ks * 32);
                    uint32_t a2 = lds_u(ab + ks * 32 + 16);
                    uint32_t a1 = lds_u(ab + ks * 32 + 640);
                    uint32_t a3 = lds_u(ab + ks * 32 + 656);
                    const float* wk = wb + ks * 512;
                    #pragma unroll
                    for (int nt = 0; nt < 8; nt++) {
                        uint2 b = __ldg((const uint2*)(wk + nt * 64));
                        mma_tf32(d[nt], a0, a1, a2, a3, b.x, b.y);
                    }
                }
            }
        }
    }

    // epilogue: tanh + tf32-round, store to h chunks
    const int zp = z0 + 1, yp = y0 + yw + 1;
    const int hrow = ((zp * PD + yp) * PD + 1 + x0w) * 8 + (lane >> 2) * 8 + c0;
    #pragma unroll
    for (int nt = 0; nt < 8; nt++) {
        int a0i = nt * HCH + hrow;
        float2 lo, hi;
        lo.x = __uint_as_float(cvt_tf32(tanhf(d[nt][0])));
        lo.y = __uint_as_float(cvt_tf32(tanhf(d[nt][1])));
        hi.x = __uint_as_float(cvt_tf32(tanhf(d[nt][2])));
        hi.y = __uint_as_float(cvt_tf32(tanhf(d[nt][3])));
        *(float2*)&g_h[a0i]      = lo;
        *(float2*)&g_h[a0i + 64] = hi;
    }
}

// ---------------------------------------------------------------------------
// Conv2 (64 -> 16) + fused Euler update (writes g_ypad fp32 + g_ytf32).
// h already tf32 bits -> no cvt in mainloop.
// ---------------------------------------------------------------------------
__device__ __forceinline__ void load_chunk2(uint32_t buf, int ch,
                                            int y0, int z0, int tid) {
    const float* base = g_h + ch * HCH;
    for (int i = tid; i < 12 * 66; i += 256) {
        int row = i / 66, xp = i % 66;
        int zi = row >> 2, yi = row & 3;
        const float* src = base + ((((z0 + zi) * PD) + y0 + yi) * PD + xp) * 8;
        uint32_t dst = buf + (uint32_t)(row * T2ROW + xp * 48);
        cp16(dst,      src);
        cp16(dst + 16, src + 4);
    }
}

__global__ __launch_bounds__(256, 2)
void conv2_k(const float* __restrict__ b2, const float* __restrict__ nz) {
    extern __shared__ float sm[];
    const int tid = threadIdx.x, lane = tid & 31, w = tid >> 5;
    const int x0w = (w & 3) * 16, yw = w >> 2;
    const int y0 = blockIdx.x * 2, z0 = blockIdx.y;

    const uint32_t tb = (uint32_t)__cvta_generic_to_shared(sm);

    float d[2][4];
    #pragma unroll
    for (int nt = 0; nt < 2; nt++)
        d[nt][0] = d[nt][1] = d[nt][2] = d[nt][3] = 0.f;

    const uint32_t loff = (uint32_t)((lane >> 2) * 48 + (lane & 3) * 4);

    load_chunk2(tb, 0, y0, z0, tid);
    cp_commit();

    #pragma unroll 1
    for (int ch = 0; ch < 8; ch++) {
        __syncthreads();
        if (ch + 1 < 8) {
            load_chunk2(tb + (uint32_t)(((ch + 1) & 1) * T2SZ),
                        ch + 1, y0, z0, tid);
            cp_commit();
            cp_wait<1>();
        } else {
            cp_wait<0>();
        }
        __syncthreads();

        const uint32_t cb = tb + (uint32_t)((ch & 1) * T2SZ);
        const float* wch = g_wf2 + ch * 3456 + lane * 2;

        #pragma unroll 1
        for (int dz = 0; dz < 3; dz++) {
            #pragma unroll
            for (int dy = 0; dy < 3; dy++) {
                const uint32_t rbase = cb + (uint32_t)((dz * 4 + yw + dy) * T2ROW);
                const int tap = (dz * 3 + dy) * 3;
                #pragma unroll
                for (int dx = 0; dx < 3; dx++) {
                    const uint32_t ab = rbase + (uint32_t)((x0w + dx) * 48) + loff;
                    uint32_t a0 = lds_u(ab);
                    uint32_t a2 = lds_u(ab + 16);
                    uint32_t a1 = lds_u(ab + 384);
                    uint32_t a3 = lds_u(ab + 400);
                    const float* wt = wch + (tap + dx) * 128;
                    uint2 b0 = __ldg((const uint2*)(wt));
                    uint2 b1 = __ldg((const uint2*)(wt + 64));
                    mma_tf32(d[0], a0, a1, a2, a3, b0.x, b0.y);
                    mma_tf32(d[1], a0, a1, a2, a3, b1.x, b1.y);
                }
            }
        }
    }

    // fused Euler update: y += (f + b2)*dt + sn*z; write fp32 + tf32 shadow
    const int c0 = (lane & 3) * 2;
    const int vx = x0w + (lane >> 2);
    const int gy = y0 + yw;
    #pragma unroll
    for (int nt = 0; nt < 2; nt++) {
        int cc = nt * 8 + c0;
        float bl = __ldg(b2 + cc), bh = __ldg(b2 + cc + 1);
        #pragma unroll
        for (int half = 0; half < 2; half++) {
            int v = vx + half * 8;
            int yi = (((z0 + 1) * PD + gy + 1) * PD + (v + 1)) * 16 + cc;
            int ni = (z0 * 64 + gy) * 64 + v;
            float2 yv = *(const float2*)&g_ypad[yi];
            float znl = __ldg(&nz[cc * SSS + ni]);
            float znh = __ldg(&nz[(cc + 1) * SSS + ni]);
            yv.x += (d[nt][half * 2 + 0] + bl) * DT_F + SN_F * znl;
            yv.y += (d[nt][half * 2 + 1] + bh) * DT_F + SN_F * znh;
            *(float2*)&g_ypad[yi] = yv;
            float2 yt;
            yt.x = __uint_as_float(cvt_tf32(yv.x));
            yt.y = __uint_as_float(cvt_tf32(yv.y));
            *(float2*)&g_ytf32[yi] = yt;
        }
    }
}

// ---------------------------------------------------------------------------
// Launch: inputs = [x, integration_time, w1, b1, w2, b2, noise]
// ---------------------------------------------------------------------------
extern "C" void kernel_launch(void* const* d_in, const int* in_sizes, int n_in,
                              void* d_out, int out_size) {
    const float* x  = (const float*)d_in[0];
    const float* w1 = (const float*)d_in[2];
    const float* b1 = (const float*)d_in[3];
    const float* w2 = (const float*)d_in[4];
    const float* b2 = (const float*)d_in[5];
    const float* nz = (const float*)d_in[6];

    cudaFuncSetAttribute(conv1_k,
        cudaFuncAttributeMaxDynamicSharedMemorySize, T1SZ);
    cudaFuncSetAttribute(conv2_k,
        cudaFuncAttributeMaxDynamicSharedMemorySize, 2 * T2SZ);

    reorder_k<<<(27648 + 255) / 256, 256>>>(w1, w2);
    pack_k<<<NELEM / 256, 256>>>(x);

    dim3 cgrid(32, 64);
    for (int s = 0; s < NSTEPS; s++) {
        conv1_k<<<cgrid, 256, T1SZ>>>(b1);
        conv2_k<<<cgrid, 256, 2 * T2SZ>>>(b2, nz + (size_t)s * NELEM);
    }

    unpack_k<<<NELEM / 256, 256>>>((float*)d_out);
}

// round 14
// speedup vs baseline: 2.2723x; 1.1760x over previous
#include <cuda_runtime.h>
#include <math.h>
#include <stdint.h>

// ---------------- problem constants ----------------
#define S     64
#define SS    (S*S)
#define SSS   (S*S*S)
#define C_IN  16
#define C_HID 64
#define NELEM (C_IN*SSS)       // 4194304
#define NSTEPS 20
#define DT_F   0.05f
#define SN_F   (0.1f * 0.22360679774997896f)

#define PD    66               // padded side (zero shell)
#define PCH   (PD*PD*PD)       // 287496 voxels padded
#define HCH   (PCH*8)          // floats per 8-channel h chunk

// conv1 tile: x:64, y:2, z:1 (M=128), 8 warps (unchanged)
#define T1ROW 5280             // 66*20*4 bytes per (z,y) row
#define T1SZ  63360            // 12 rows
// conv2 tile: x:64, y:4, z:2 (M=512), 8 warps, M=64/warp
// row = one (z,y): [plane0: 66 vox x 4ch x 4B][plane1: same] = 2112 B
#define T2ROW 2112
#define P2OFF 1056             // plane1 byte offset within row
#define T2NR  24               // 4 z x 6 y rows
#define T2SZ  (T2NR*T2ROW)     // 50688 B per chunk buffer

// ---------------- device scratch (allocation-free; zero-init shells) -------
__device__ float g_ypad[PCH*16];        // y fp32 state, padded CL [z][y][x][16]
__device__ float g_ytf32[PCH*16];       // tf32-rounded shadow (conv1 input)
__device__ float g_h[HCH*8];            // h, 8 chunks of [z][y][x][8] (tf32 bits)
__device__ float g_wf1[27*2*8*32*2];    // conv1 B-frags [tap][ks][nt][lane][2]
__device__ float g_wf2[8*27*2*32*2];    // conv2 B-frags [ch][tap][nt][lane][2]

// ---------------- PTX helpers ----------------
__device__ __forceinline__ uint32_t cvt_tf32(float f) {
    uint32_t r;
    asm("cvt.rna.tf32.f32 %0, %1;" : "=r"(r) : "f"(f));
    return r;
}
__device__ __forceinline__ uint32_t lds_u(uint32_t a) {
    uint32_t v;
    asm volatile("ld.shared.b32 %0, [%1];" : "=r"(v) : "r"(a));
    return v;
}
__device__ __forceinline__ void mma_tf32(float* d, uint32_t a0, uint32_t a1,
                                         uint32_t a2, uint32_t a3,
                                         uint32_t b0, uint32_t b1) {
    asm volatile(
        "mma.sync.aligned.m16n8k8.row.col.f32.tf32.tf32.f32 "
        "{%0,%1,%2,%3}, {%4,%5,%6,%7}, {%8,%9}, {%0,%1,%2,%3};"
        : "+f"(d[0]), "+f"(d[1]), "+f"(d[2]), "+f"(d[3])
        : "r"(a0), "r"(a1), "r"(a2), "r"(a3), "r"(b0), "r"(b1));
}
__device__ __forceinline__ void cp16(uint32_t dst, const void* src) {
    asm volatile("cp.async.cg.shared.global [%0], [%1], 16;"
                 :: "r"(dst), "l"(src));
}
__device__ __forceinline__ void cp_commit() {
    asm volatile("cp.async.commit_group;");
}
template<int N> __device__ __forceinline__ void cp_wait() {
    asm volatile("cp.async.wait_group %0;" :: "n"(N));
}

// ---------------------------------------------------------------------------
// Weight reorder into mma B-fragment layout (tf32-rounded).
// ---------------------------------------------------------------------------
__global__ void reorder_k(const float* __restrict__ w1,
                          const float* __restrict__ w2) {
    int i = blockIdx.x * blockDim.x + threadIdx.x;
    if (i >= 27648) return;
    {   // conv1: w1[oc64][ic16][27]
        int j = i & 1, lane = (i >> 1) & 31, nt = (i >> 6) & 7,
            ks = (i >> 9) & 1, tap = i >> 10;
        int oc = nt * 8 + (lane >> 2);
        int ic = ks * 8 + (lane & 3) + j * 4;
        g_wf1[i] = __uint_as_float(cvt_tf32(w1[(oc * 16 + ic) * 27 + tap]));
    }
    {   // conv2: w2[oc16][ic64][27]
        int j = i & 1, lane = (i >> 1) & 31, nt = (i >> 6) & 1;
        int t2 = i >> 7, tap = t2 % 27, ch = t2 / 27;
        int oc = nt * 8 + (lane >> 2);
        int ic = ch * 8 + (lane & 3) + j * 4;
        g_wf2[i] = __uint_as_float(cvt_tf32(w2[(oc * 64 + ic) * 27 + tap]));
    }
}

// ---------------------------------------------------------------------------
// Pack / unpack
// ---------------------------------------------------------------------------
__global__ void pack_k(const float* __restrict__ xin) {
    int e = blockIdx.x * blockDim.x + threadIdx.x;
    if (e >= NELEM) return;
    int c = e & 15, v = e >> 4;
    int x = v & 63, y = (v >> 6) & 63, z = v >> 12;
    float val = xin[c * SSS + v];
    int pi = ((((z + 1) * PD) + y + 1) * PD + x + 1) * 16 + c;
    g_ypad[pi]  = val;
    g_ytf32[pi] = __uint_as_float(cvt_tf32(val));
}
__global__ void unpack_k(float* __restrict__ out) {
    int e = blockIdx.x * blockDim.x + threadIdx.x;
    if (e >= NELEM) return;
    int c = e & 15, v = e >> 4;
    int x = v & 63, y = (v >> 6) & 63, z = v >> 12;
    out[c * SSS + v] = g_ypad[((((z + 1) * PD) + y + 1) * PD + x + 1) * 16 + c];
}

// ---------------------------------------------------------------------------
// Conv1 (16 -> 64) + bias + tanh -> g_h (tf32 bits, chunked CL). Unchanged.
// ---------------------------------------------------------------------------
__global__ __launch_bounds__(256, 2)
void conv1_k(const float* __restrict__ b1) {
    extern __shared__ float sm[];
    const int tid = threadIdx.x, lane = tid & 31, w = tid >> 5;
    const int x0w = (w & 3) * 16, yw = w >> 2;
    const int y0 = blockIdx.x * 2, z0 = blockIdx.y;

    const uint32_t tb = (uint32_t)__cvta_generic_to_shared(sm);

    for (int i = tid; i < 12 * 66; i += 256) {
        int row = i / 66, xp = i % 66;
        int zi = row >> 2, yi = row & 3;
        const float* src = g_ytf32 +
            ((((z0 + zi) * PD) + y0 + yi) * PD + xp) * 16;
        uint32_t dst = tb + (uint32_t)(row * T1ROW + xp * 80);
        cp16(dst,      src);
        cp16(dst + 16, src + 4);
        cp16(dst + 32, src + 8);
        cp16(dst + 48, src + 12);
    }
    cp_commit(); cp_wait<0>();
    __syncthreads();

    float d[8][4];
    const int c0 = (lane & 3) * 2;
    #pragma unroll
    for (int nt = 0; nt < 8; nt++) {
        float bl = __ldg(b1 + nt * 8 + c0), bh = __ldg(b1 + nt * 8 + c0 + 1);
        d[nt][0] = bl; d[nt][1] = bh; d[nt][2] = bl; d[nt][3] = bh;
    }

    const uint32_t loff = (uint32_t)((lane >> 2) * 80 + (lane & 3) * 4);

    #pragma unroll 1
    for (int dz = 0; dz < 3; dz++) {
        #pragma unroll 1
        for (int dy = 0; dy < 3; dy++) {
            const uint32_t rbase = tb + (uint32_t)((dz * 4 + yw + dy) * T1ROW);
            const int tap = (dz * 3 + dy) * 3;
            #pragma unroll
            for (int dx = 0; dx < 3; dx++) {
                const uint32_t ab = rbase + (uint32_t)((x0w + dx) * 80) + loff;
                const float* wb = g_wf1 + (tap + dx) * 1024 + lane * 2;
                #pragma unroll
                for (int ks = 0; ks < 2; ks++) {
                    uint32_t a0 = lds_u(ab + ks * 32);
                    uint32_t a2 = lds_u(ab + ks * 32 + 16);
                    uint32_t a1 = lds_u(ab + ks * 32 + 640);
                    uint32_t a3 = lds_u(ab + ks * 32 + 656);
                    const float* wk = wb + ks * 512;
                    #pragma unroll
                    for (int nt = 0; nt < 8; nt++) {
                        uint2 b = __ldg((const uint2*)(wk + nt * 64));
                        mma_tf32(d[nt], a0, a1, a2, a3, b.x, b.y);
                    }
                }
            }
        }
    }

    const int zp = z0 + 1, yp = y0 + yw + 1;
    const int hrow = ((zp * PD + yp) * PD + 1 + x0w) * 8 + (lane >> 2) * 8 + c0;
    #pragma unroll
    for (int nt = 0; nt < 8; nt++) {
        int a0i = nt * HCH + hrow;
        float2 lo, hi;
        lo.x = __uint_as_float(cvt_tf32(tanhf(d[nt][0])));
        lo.y = __uint_as_float(cvt_tf32(tanhf(d[nt][1])));
        hi.x = __uint_as_float(cvt_tf32(tanhf(d[nt][2])));
        hi.y = __uint_as_float(cvt_tf32(tanhf(d[nt][3])));
        *(float2*)&g_h[a0i]      = lo;
        *(float2*)&g_h[a0i + 64] = hi;
    }
}

// ---------------------------------------------------------------------------
// Conv2 (64 -> 16) + fused Euler update.  Tile x:64,y:4,z:2; warp = one
// (y,z) row, M=64 (4 m-tiles) -> 8 independent MMA chains.  k-plane-split
// SMEM rows -> conflict-free 16B/voxel A loads.
// ---------------------------------------------------------------------------
__device__ __forceinline__ void load_chunk2(uint32_t buf, int ch,
                                            int y0, int z0, int tid) {
    const float* base = g_h + ch * HCH;
    for (int i = tid; i < T2NR * 66; i += 256) {
        int row = i / 66, xp = i % 66;
        int zi = row / 6, yi = row % 6;
        const float* src = base + ((((z0 + zi) * PD) + y0 + yi) * PD + xp) * 8;
        uint32_t dst = buf + (uint32_t)(row * T2ROW + xp * 16);
        cp16(dst,         src);       // ch 0-3 -> plane 0
        cp16(dst + P2OFF, src + 4);   // ch 4-7 -> plane 1
    }
}

__global__ __launch_bounds__(256, 2)
void conv2_k(const float* __restrict__ b2, const float* __restrict__ nz) {
    extern __shared__ float sm[];
    const int tid = threadIdx.x, lane = tid & 31, w = tid >> 5;
    const int yw = w & 3, zw = w >> 2;
    const int y0 = blockIdx.x * 4, z0 = blockIdx.y * 2;

    const uint32_t tb = (uint32_t)__cvta_generic_to_shared(sm);

    float d[4][2][4];
    #pragma unroll
    for (int mt = 0; mt < 4; mt++)
        #pragma unroll
        for (int nt = 0; nt < 2; nt++)
            d[mt][nt][0] = d[mt][nt][1] = d[mt][nt][2] = d[mt][nt][3] = 0.f;

    const uint32_t loff = (uint32_t)((lane >> 2) * 16 + (lane & 3) * 4);

    load_chunk2(tb, 0, y0, z0, tid);
    cp_commit();

    #pragma unroll 1
    for (int ch = 0; ch < 8; ch++) {
        __syncthreads();
        if (ch + 1 < 8) {
            load_chunk2(tb + (uint32_t)(((ch + 1) & 1) * T2SZ),
                        ch + 1, y0, z0, tid);
            cp_commit();
            cp_wait<1>();
        } else {
            cp_wait<0>();
        }
        __syncthreads();

        const uint32_t cb = tb + (uint32_t)((ch & 1) * T2SZ);
        const float* wch = g_wf2 + ch * 3456 + lane * 2;

        #pragma unroll 1
        for (int dz = 0; dz < 3; dz++) {
            #pragma unroll 1
            for (int dy = 0; dy < 3; dy++) {
                const uint32_t rbase =
                    cb + (uint32_t)(((zw + dz) * 6 + yw + dy) * T2ROW) + loff;
                const int tap = (dz * 3 + dy) * 3;
                #pragma unroll
                for (int dx = 0; dx < 3; dx++) {
                    const float* wt = wch + (tap + dx) * 128;
                    uint2 b0 = __ldg((const uint2*)(wt));
                    uint2 b1 = __ldg((const uint2*)(wt + 64));
                    #pragma unroll
                    for (int mt = 0; mt < 4; mt++) {
                        const uint32_t ab =
                            rbase + (uint32_t)((mt * 16 + dx) * 16);
                        uint32_t a0 = lds_u(ab);
                        uint32_t a1 = lds_u(ab + 128);           // +8 voxels
                        uint32_t a2 = lds_u(ab + P2OFF);         // k+4 plane
                        uint32_t a3 = lds_u(ab + P2OFF + 128);
                        mma_tf32(d[mt][0], a0, a1, a2, a3, b0.x, b0.y);
                        mma_tf32(d[mt][1], a0, a1, a2, a3, b1.x, b1.y);
                    }
                }
            }
        }
    }

    // fused Euler update: y += (f + b2)*dt + sn*z; fp32 + tf32 shadow
    const int c0 = (lane & 3) * 2;
    const int r  = lane >> 2;
    const int gy = y0 + yw, gz = z0 + zw;
    float bl[2], bh[2];
    #pragma unroll
    for (int nt = 0; nt < 2; nt++) {
        bl[nt] = __ldg(b2 + nt * 8 + c0);
        bh[nt] = __ldg(b2 + nt * 8 + c0 + 1);
    }
    #pragma unroll
    for (int mt = 0; mt < 4; mt++) {
        #pragma unroll
        for (int nt = 0; nt < 2; nt++) {
            int cc = nt * 8 + c0;
            #pragma unroll
            for (int half = 0; half < 2; half++) {
                int v  = mt * 16 + r + half * 8;
                int yi = (((gz + 1) * PD + gy + 1) * PD + (v + 1)) * 16 + cc;
                int ni = (gz * 64 + gy) * 64 + v;
                float2 yv = *(const float2*)&g_ypad[yi];
                float znl = __ldg(&nz[cc * SSS + ni]);
                float znh = __ldg(&nz[(cc + 1) * SSS + ni]);
                yv.x += (d[mt][nt][half * 2 + 0] + bl[nt]) * DT_F + SN_F * znl;
                yv.y += (d[mt][nt][half * 2 + 1] + bh[nt]) * DT_F + SN_F * znh;
                *(float2*)&g_ypad[yi] = yv;
                float2 yt;
                yt.x = __uint_as_float(cvt_tf32(yv.x));
                yt.y = __uint_as_float(cvt_tf32(yv.y));
                *(float2*)&g_ytf32[yi] = yt;
            }
        }
    }
}

// ---------------------------------------------------------------------------
// Launch: inputs = [x, integration_time, w1, b1, w2, b2, noise]
// ---------------------------------------------------------------------------
extern "C" void kernel_launch(void* const* d_in, const int* in_sizes, int n_in,
                              void* d_out, int out_size) {
    const float* x  = (const float*)d_in[0];
    const float* w1 = (const float*)d_in[2];
    const float* b1 = (const float*)d_in[3];
    const float* w2 = (const float*)d_in[4];
    const float* b2 = (const float*)d_in[5];
    const float* nz = (const float*)d_in[6];

    cudaFuncSetAttribute(conv1_k,
        cudaFuncAttributeMaxDynamicSharedMemorySize, T1SZ);
    cudaFuncSetAttribute(conv2_k,
        cudaFuncAttributeMaxDynamicSharedMemorySize, 2 * T2SZ);

    reorder_k<<<(27648 + 255) / 256, 256>>>(w1, w2);
    pack_k<<<NELEM / 256, 256>>>(x);

    dim3 cgrid1(32, 64);   // conv1: y:2 x z:1 tiles
    dim3 cgrid2(16, 32);   // conv2: y:4 x z:2 tiles
    for (int s = 0; s < NSTEPS; s++) {
        conv1_k<<<cgrid1, 256, T1SZ>>>(b1);
        conv2_k<<<cgrid2, 256, 2 * T2SZ>>>(b2, nz + (size_t)s * NELEM);
    }

    unpack_k<<<NELEM / 256, 256>>>((float*)d_out);
}